// round 11
// baseline (speedup 1.0000x reference)
#include <cuda_runtime.h>
#include <cstddef>

// ChebychevTransform: x[8,256,256,8] f32 -> out[8,256,256,128] f32
// out[b,h,w, c*16 + p*4 + k] = sum_{i,j} T[p,j]*T[k,i]*x[b,h+i-1,w+j-1,c]
// (zero pad: 1 before / 2 after, TF SAME n=4)
// T = [[1/6,1/3,1/3,1/6],[1/3,1/3,-1/3,-1/3],[1/3,-1/3,-1/3,1/3],[1/3,-2/3,2/3,-1/3]]
//
// Block = 256 threads = one (b, 8-row strip, 32 w-columns).
// Stage:   input halo tile (11 rows x 35 cols x 8 ch) into smem, transposed to
//          [t][c][wcol] with wcol stride padded to 36 -> conflict-free STS/LDS,
//          16B-aligned float4 reads. W-padding zeroed at staging time.
// Consume: warp = 4 adjacent columns (wl = wid*4); lane = (p=lane>>3, c=lane&7).
//          Per row t: two LDS.128 fetch words wl..wl+7 of (t,c); the 4 pixels'
//          tap windows are register slices of (A,B). 4-FMA dot with T[p,:],
//          vertical ring per column, dense .cs STG.128 at (c*16+p*4).

#define HH 256
#define WW 256
#define CC 8
#define ROWF (WW * CC)       // floats per image row
#define TCOLS 35             // staged w-columns (w0-1 .. w0+33)
#define TPAD 36              // padded stride (bank-conflict-free)
#define NT 11                // staged rows (h0-1 .. h0+9)

__device__ __forceinline__ void cheb4(float x0, float x1, float x2, float x3,
                                      float& y0, float& y1, float& y2, float& y3) {
    const float K3 = 1.0f / 3.0f;
    const float K6 = 1.0f / 6.0f;
    float s0 = x0 + x3, s1 = x1 + x2;
    float d0 = x0 - x3, d1 = x1 - x2;
    y0 = fmaf(s1, K3, s0 * K6);
    y1 = (d0 + d1) * K3;
    y2 = (s0 - s1) * K3;
    y3 = fmaf(d1, -2.0f, d0) * K3;
}

__global__ __launch_bounds__(256, 4)
void cheb_kernel(const float* __restrict__ x, float* __restrict__ out) {
    __shared__ __align__(16) float tile[NT * CC * TPAD];  // [t][c][wcol], 12672B

    int bx = blockIdx.x;
    int wt = bx & 7;            // 8 w-tiles of 32
    int hs = (bx >> 3) & 31;    // 32 h-strips of 8
    int b  = bx >> 8;
    int w0 = wt * 32;
    int h0 = hs * 8;

    const float* src = x + (size_t)b * HH * ROWF / CC * CC;  // b*H*W*C
    // (simplify): base of batch b
    src = x + (size_t)b * HH * WW * CC;

    // ---- staging: 3080 floats, coalesced LDG, transposed conflict-free STS ----
    for (int e = threadIdx.x; e < NT * TCOLS * CC; e += 256) {
        int c    = e & 7;
        int tw   = e >> 3;           // t*35 + wcol
        int t    = tw / TCOLS;
        int wcol = tw - t * TCOLS;
        int r  = min(max(h0 - 1 + t, 0), HH - 1);
        int wc = w0 - 1 + wcol;
        float v = (wc >= 0 && wc < WW)
                    ? src[(size_t)r * ROWF + wc * CC + c] : 0.0f;
        tile[t * (CC * TPAD) + c * TPAD + wcol] = v;
    }
    __syncthreads();

    // ---- consume ----
    int lane = threadIdx.x & 31;
    int wid  = threadIdx.x >> 5;
    int p  = lane >> 3;          // output row index of T
    int c  = lane & 7;           // channel
    int wl = wid * 4;            // first of this warp's 4 pixel columns

    // lane's horizontal Chebyshev row T[p,:]
    const float K3 = 1.0f / 3.0f, K6 = 1.0f / 6.0f, K23 = 2.0f / 3.0f;
    float t0 = (p == 0) ? K6 : K3;
    float t1 = (p <= 1) ? K3 : (p == 2 ? -K3 : -K23);
    float t2 = (p == 0) ? K3 : (p == 3 ? K23 : -K3);
    float t3 = (p == 0) ? K6 : (p == 2 ? K3 : -K3);

    float ring[4][4];
    float* outbase = out + ((size_t)(b * HH + h0) * WW + (w0 + wl)) * 128
                         + (c * 16 + p * 4);

    #pragma unroll
    for (int t = 0; t < NT; t++) {
        const float4* tp =
            (const float4*)&tile[t * (CC * TPAD) + c * TPAD + wl];
        float4 A = tp[0];
        float4 B = tp[1];

        int r = h0 - 1 + t;
        bool rv = (r >= 0) && (r < HH);

        // horizontal dot for the 4 pixel columns (tap windows slide by 1)
        float h0v = fmaf(t0, A.x, fmaf(t1, A.y, fmaf(t2, A.z, t3 * A.w)));
        float h1v = fmaf(t0, A.y, fmaf(t1, A.z, fmaf(t2, A.w, t3 * B.x)));
        float h2v = fmaf(t0, A.z, fmaf(t1, A.w, fmaf(t2, B.x, t3 * B.y)));
        float h3v = fmaf(t0, A.w, fmaf(t1, B.x, fmaf(t2, B.y, t3 * B.z)));
        if (!rv) { h0v = 0.0f; h1v = 0.0f; h2v = 0.0f; h3v = 0.0f; }

        ring[0][t & 3] = h0v;
        ring[1][t & 3] = h1v;
        ring[2][t & 3] = h2v;
        ring[3][t & 3] = h3v;

        if (t >= 3) {
            int s = t - 3;   // output row within strip
            float* orow = outbase + (size_t)s * (WW * 128);
            #pragma unroll
            for (int q = 0; q < 4; q++) {
                float4 o;
                cheb4(ring[q][(t - 3) & 3], ring[q][(t - 2) & 3],
                      ring[q][(t - 1) & 3], ring[q][t & 3],
                      o.x, o.y, o.z, o.w);
                __stcs((float4*)(orow + q * 128), o);
            }
        }
    }
}

extern "C" void kernel_launch(void* const* d_in, const int* in_sizes, int n_in,
                              void* d_out, int out_size) {
    const float* x = (const float*)d_in[0];
    float* out = (float*)d_out;
    // 8 b * 32 hs * 8 wt = 2048 blocks of 256 threads
    cheb_kernel<<<2048, 256>>>(x, out);
}